// round 11
// baseline (speedup 1.0000x reference)
#include <cuda_runtime.h>
#include <stdint.h>

// Energy4D: 4x multi-resolution hash-grid encodings (instant-NGP style).
// L=16 levels, F=2 feats, HMAP=2^19, BASE=32, GROWTH=2 -> res_l = 32<<l.
//
// R10 -> R11: fix "too many resources" — scan_kernel used a 64-int local
// array at 1024 threads (>64K regs/SM). Rewritten as a two-pass scan with
// no local array. Sort theory unchanged: Morton counting sort (quantized
// ux,uy,uz,ut) makes warps of neighbors share grid cells at levels 0-11,
// collapsing intra-warp gather divergence. Levels 12-15 stay identity order
// (measured at the L1tex wavefront floor, 109us). Values bit-identical:
// only the processing ORDER changes; outputs scatter to original slots.
//
// Numerics must match XLA bit-for-bit: x/const -> x*rn(1/const);
// w = rn(u*resm1) - p0_clip; all __f*_rn (immune to --use_fast_math).

constexpr unsigned HMASK = (1u << 19) - 1u;
constexpr unsigned P1 = 2654435761u;
constexpr unsigned P2 = 805459861u;
constexpr int NPTS = 262144;
constexpr int NBINS = 65536;

__device__ int g_hist[NBINS];
__device__ unsigned short g_key[NPTS];
__device__ int g_perm[NPTS];

__device__ __host__ constexpr int level_offset(int l) {
    return (l == 0) ? 0 : (l == 1) ? 32768 : 294912 + (l - 2) * 524288;
}

__device__ __forceinline__ float clip01(float v) {
    return fminf(fmaxf(v, 0.0f), 1.0f);
}

// Table gather: non-coherent load with L2 evict-last cache hint.
__device__ __forceinline__ float2 ldg_tbl(const float2* p, uint64_t pol) {
    float2 v;
    asm("ld.global.nc.L2::cache_hint.v2.f32 {%0,%1}, [%2], %3;"
        : "=f"(v.x), "=f"(v.y) : "l"(p), "l"(pol));
    return v;
}

// Streaming 16B store (evict-first).
__device__ __forceinline__ void st_cs4(float4* p, float4 v) {
    asm volatile("st.global.cs.v4.f32 [%0], {%1,%2,%3,%4};"
                 :: "l"(p), "f"(v.x), "f"(v.y), "f"(v.z), "f"(v.w) : "memory");
}

// Shared u-computation (bit-exact vs XLA; also reused for sort keys).
__device__ __forceinline__ void compute_u(float4 c, float4 r,
                                          float& ux, float& uy, float& uz, float& ut) {
    const float R180   = 1.0f / 180.0f;
    const float R360   = 1.0f / 360.0f;
    const float R20000 = 1.0f / 20000.0f;
    float nx = clip01(__fmul_rn(__fadd_rn(__fsub_rn(c.x, r.x), 90.0f),    R180));
    float ny = clip01(__fmul_rn(__fadd_rn(__fsub_rn(c.y, r.y), 180.0f),   R360));
    float nz = clip01(__fmul_rn(__fadd_rn(__fsub_rn(c.z, r.z), 11000.0f), R20000));
    float nt = clip01(__fsub_rn(c.w, r.w));
    float tsn = __fmul_rn(__fsub_rn(__fmul_rn(nt, 2.0f), 1.0f), 0.9f);
    ux = clip01(__fmul_rn(__fadd_rn(nx,  1.0f), 0.5f));
    uy = clip01(__fmul_rn(__fadd_rn(ny,  1.0f), 0.5f));
    uz = clip01(__fmul_rn(__fadd_rn(nz,  1.0f), 0.5f));
    ut = clip01(__fmul_rn(__fadd_rn(tsn, 1.0f), 0.5f));
}

// ---------------- sort: zero -> key+hist -> scan -> scatter ----------------

__global__ void zero_hist_kernel() {
    g_hist[blockIdx.x * blockDim.x + threadIdx.x] = 0;
}

__device__ __forceinline__ unsigned spread4(unsigned v) {
    v = (v | (v << 6)) & 0x0303u;
    v = (v | (v << 3)) & 0x1111u;
    return v;
}

__device__ __forceinline__ int quant16(float v, float lo, float inv_w) {
    int q = (int)((v - lo) * inv_w);
    return min(max(q, 0), 15);
}

__global__ void key_hist_kernel(const float4* __restrict__ coords,
                                const float4* __restrict__ refc) {
    int i = blockIdx.x * blockDim.x + threadIdx.x;
    float ux, uy, uz, ut;
    compute_u(coords[i], refc[i], ux, uy, uz, ut);
    // +-4 sigma ranges of the u's (sigma_ux=0.0014, uy=0.0007, uz=0.00125;
    // ut in [0.05, ~0.23] with half the mass exactly at 0.05).
    int qx = quant16(ux, 0.7444f, 16.0f / 0.0112f);
    int qy = quant16(uy, 0.7472f, 16.0f / 0.0056f);
    int qz = quant16(uz, 0.7700f, 16.0f / 0.0100f);
    int qt = quant16(ut, 0.0500f, 16.0f / 0.1600f);
    unsigned key = spread4(qx) | (spread4(qy) << 1) | (spread4(qz) << 2) | (spread4(qt) << 3);
    g_key[i] = (unsigned short)key;
    atomicAdd(&g_hist[key], 1);
}

// Two-pass scan, no per-thread local array (regs stay small at 1024 thr).
__global__ __launch_bounds__(1024) void scan_kernel() {
    __shared__ int ssum[1024];
    const int t = threadIdx.x;
    const int base = t * 64;
    // pass 1: chunk sums
    int s = 0;
    for (int k = 0; k < 64; ++k) s += g_hist[base + k];
    ssum[t] = s;
    __syncthreads();
    // Hillis-Steele inclusive scan over 1024 partials
    for (int off = 1; off < 1024; off <<= 1) {
        int x = (t >= off) ? ssum[t - off] : 0;
        __syncthreads();
        ssum[t] += x;
        __syncthreads();
    }
    int run = ssum[t] - s;   // exclusive prefix for this thread's chunk
    // pass 2: rewrite bins with running exclusive prefix
    for (int k = 0; k < 64; ++k) {
        int v = g_hist[base + k];
        g_hist[base + k] = run;
        run += v;
    }
}

__global__ void scatter_kernel() {
    int i = blockIdx.x * blockDim.x + threadIdx.x;
    int pos = atomicAdd(&g_hist[g_key[i]], 1);
    g_perm[pos] = i;
}

// ---------------- main encode kernels ----------------

template <int L0, int NLEV, bool USE_PERM>
__global__ __launch_bounds__(256) void energy4d_group_kernel(
    const float4* __restrict__ coords,
    const float4* __restrict__ refc,
    const float2* __restrict__ t0,
    const float2* __restrict__ t1,
    const float2* __restrict__ t2,
    const float2* __restrict__ t3,
    float2* __restrict__ out)   // out as float2: elem = pt*64 + e*16 + l
{
    const int warp = threadIdx.x >> 5;
    const int lane = threadIdx.x & 31;
    const int e    = warp & 3;                               // encoding id
    const int slot = (blockIdx.x * 2 + (warp >> 2)) * 32 + lane;
    const int pt   = USE_PERM ? g_perm[slot] : slot;

    uint64_t pol;
    asm("createpolicy.fractional.L2::evict_last.b64 %0, 1.0;" : "=l"(pol));

    float ux, uy, uz, ut;
    compute_u(coords[pt], refc[pt], ux, uy, uz, ut);

    // encoding dim selection: e0=(x,y,z) e1=(x,y,t) e2=(y,z,t) e3=(x,z,t)
    const float ua = (e == 2) ? uy : ux;
    const float ub = (e <= 1) ? uy : uz;
    const float uc = (e == 0) ? uz : ut;
    const float2* __restrict__ tbl =
        (e == 0) ? t0 : (e == 1) ? t1 : (e == 2) ? t2 : t3;

    float2 acc[NLEV];

    #pragma unroll
    for (int j = 0; j < NLEV; ++j) {
        const int   l     = L0 + j;
        const int   res   = 32 << l;
        const float resm1 = (float)(res - 1);
        const int   off   = level_offset(l);

        float pa = __fmul_rn(ua, resm1);
        float pb = __fmul_rn(ub, resm1);
        float pc = __fmul_rn(uc, resm1);
        int a0 = min(max((int)floorf(pa), 0), res - 2);
        int b0 = min(max((int)floorf(pb), 0), res - 2);
        int c0 = min(max((int)floorf(pc), 0), res - 2);
        float wa = __fsub_rn(pa, (float)a0);
        float wb = __fsub_rn(pb, (float)b0);
        float wc = __fsub_rn(pc, (float)c0);

        int idx[8];
        if (l >= 2) {
            unsigned ha0 = (unsigned)a0,      ha1 = ha0 + 1u;
            unsigned hb0 = (unsigned)b0 * P1, hb1 = hb0 + P1;
            unsigned hc0 = (unsigned)c0 * P2, hc1 = hc0 + P2;
            idx[0] = (int)((ha0 ^ hb0 ^ hc0) & HMASK) + off;
            idx[1] = (int)((ha1 ^ hb0 ^ hc0) & HMASK) + off;
            idx[2] = (int)((ha0 ^ hb1 ^ hc0) & HMASK) + off;
            idx[3] = (int)((ha1 ^ hb1 ^ hc0) & HMASK) + off;
            idx[4] = (int)((ha0 ^ hb0 ^ hc1) & HMASK) + off;
            idx[5] = (int)((ha1 ^ hb0 ^ hc1) & HMASK) + off;
            idx[6] = (int)((ha0 ^ hb1 ^ hc1) & HMASK) + off;
            idx[7] = (int)((ha1 ^ hb1 ^ hc1) & HMASK) + off;
        } else {
            const int rr = res * res;
            int base = a0 + res * (b0 + res * c0) + off;
            idx[0] = base;
            idx[1] = base + 1;
            idx[2] = base + res;
            idx[3] = base + res + 1;
            idx[4] = base + rr;
            idx[5] = base + rr + 1;
            idx[6] = base + rr + res;
            idx[7] = base + rr + res + 1;
        }

        float2 f[8];
        #pragma unroll
        for (int i = 0; i < 8; ++i) f[i] = ldg_tbl(&tbl[idx[i]], pol);

        const float oma = __fsub_rn(1.0f, wa);
        const float omb = __fsub_rn(1.0f, wb);
        const float omc = __fsub_rn(1.0f, wc);
        float accx = 0.0f, accy = 0.0f;
        #pragma unroll
        for (int i = 0; i < 8; ++i) {
            float cwa = (i & 1) ? wa : oma;
            float cwb = (i & 2) ? wb : omb;
            float cwc = (i & 4) ? wc : omc;
            float cw  = __fmul_rn(__fmul_rn(cwa, cwb), cwc);
            accx = __fadd_rn(accx, __fmul_rn(f[i].x, cw));
            accy = __fadd_rn(accy, __fmul_rn(f[i].y, cw));
        }
        acc[j] = make_float2(accx, accy);
    }

    float2* optr = out + (size_t)pt * 64 + (size_t)e * 16 + L0;
    #pragma unroll
    for (int j = 0; j < NLEV; j += 2) {
        st_cs4((float4*)(optr + j),
               make_float4(acc[j].x, acc[j].y, acc[j + 1].x, acc[j + 1].y));
    }
}

extern "C" void kernel_launch(void* const* d_in, const int* in_sizes, int n_in,
                              void* d_out, int out_size) {
    const int n = in_sizes[0] / 4;          // number of points (262144)
    const float4* coords = (const float4*)d_in[0];
    const float4* refc   = (const float4*)d_in[1];
    const float2* t0 = (const float2*)d_in[2];
    const float2* t1 = (const float2*)d_in[3];
    const float2* t2 = (const float2*)d_in[4];
    const float2* t3 = (const float2*)d_in[5];
    float2* out = (float2*)d_out;

    // sort (cheap): zero -> key+hist -> scan -> scatter
    zero_hist_kernel<<<NBINS / 256, 256>>>();
    key_hist_kernel<<<n / 256, 256>>>(coords, refc);
    scan_kernel<<<1, 1024>>>();
    scatter_kernel<<<n / 256, 256>>>();

    dim3 block(256);                        // 8 warps = 2 pt-groups x 4 encodings
    dim3 grid(n / 64);
    energy4d_group_kernel<0,  4, true ><<<grid, block>>>(coords, refc, t0, t1, t2, t3, out);
    energy4d_group_kernel<4,  4, true ><<<grid, block>>>(coords, refc, t0, t1, t2, t3, out);
    energy4d_group_kernel<8,  4, true ><<<grid, block>>>(coords, refc, t0, t1, t2, t3, out);
    energy4d_group_kernel<12, 4, false><<<grid, block>>>(coords, refc, t0, t1, t2, t3, out);
}

// round 12
// speedup vs baseline: 1.3041x; 1.3041x over previous
#include <cuda_runtime.h>
#include <stdint.h>

// Energy4D: 4x multi-resolution hash-grid encodings (instant-NGP style).
// L=16 levels, F=2 feats, HMAP=2^19, BASE=32, GROWTH=2 -> res_l = 32<<l.
//
// R11 -> R12: R11's regression was sort OVERHEAD (serial 1-block scan with
// stride-64 accesses ~70-100us), leaving the dedup benefit unmeasurable.
//  (1) parallel 3-kernel scan (coalesced, ~5us)
//  (2) rebalanced Morton key: t gets 7 bits (its u-range spans ~16x more
//      grid cells than x, and 3 of 4 tables contain t), x/y/z 3 bits each.
// Encode kernels unchanged from R9 except the permuted point order for
// levels 0-11. Values bit-identical (only processing order changes).
//
// Numerics must match XLA bit-for-bit: x/const -> x*rn(1/const);
// w = rn(u*resm1) - p0_clip; all __f*_rn (immune to --use_fast_math).

constexpr unsigned HMASK = (1u << 19) - 1u;
constexpr unsigned P1 = 2654435761u;
constexpr unsigned P2 = 805459861u;
constexpr int NPTS = 262144;
constexpr int NBINS = 65536;

__device__ int g_hist[NBINS];
__device__ int g_bsum[256];
__device__ unsigned short g_key[NPTS];
__device__ int g_perm[NPTS];

__device__ __host__ constexpr int level_offset(int l) {
    return (l == 0) ? 0 : (l == 1) ? 32768 : 294912 + (l - 2) * 524288;
}

__device__ __forceinline__ float clip01(float v) {
    return fminf(fmaxf(v, 0.0f), 1.0f);
}

__device__ __forceinline__ float2 ldg_tbl(const float2* p, uint64_t pol) {
    float2 v;
    asm("ld.global.nc.L2::cache_hint.v2.f32 {%0,%1}, [%2], %3;"
        : "=f"(v.x), "=f"(v.y) : "l"(p), "l"(pol));
    return v;
}

__device__ __forceinline__ void st_cs4(float4* p, float4 v) {
    asm volatile("st.global.cs.v4.f32 [%0], {%1,%2,%3,%4};"
                 :: "l"(p), "f"(v.x), "f"(v.y), "f"(v.z), "f"(v.w) : "memory");
}

__device__ __forceinline__ void compute_u(float4 c, float4 r,
                                          float& ux, float& uy, float& uz, float& ut) {
    const float R180   = 1.0f / 180.0f;
    const float R360   = 1.0f / 360.0f;
    const float R20000 = 1.0f / 20000.0f;
    float nx = clip01(__fmul_rn(__fadd_rn(__fsub_rn(c.x, r.x), 90.0f),    R180));
    float ny = clip01(__fmul_rn(__fadd_rn(__fsub_rn(c.y, r.y), 180.0f),   R360));
    float nz = clip01(__fmul_rn(__fadd_rn(__fsub_rn(c.z, r.z), 11000.0f), R20000));
    float nt = clip01(__fsub_rn(c.w, r.w));
    float tsn = __fmul_rn(__fsub_rn(__fmul_rn(nt, 2.0f), 1.0f), 0.9f);
    ux = clip01(__fmul_rn(__fadd_rn(nx,  1.0f), 0.5f));
    uy = clip01(__fmul_rn(__fadd_rn(ny,  1.0f), 0.5f));
    uz = clip01(__fmul_rn(__fadd_rn(nz,  1.0f), 0.5f));
    ut = clip01(__fmul_rn(__fadd_rn(tsn, 1.0f), 0.5f));
}

// ---------------- sort: zero -> key+hist -> scan(A,B,C) -> scatter --------

__global__ void zero_hist_kernel() {
    g_hist[blockIdx.x * blockDim.x + threadIdx.x] = 0;
}

__device__ __forceinline__ int quantn(float v, float lo, float inv_w, int maxq) {
    int q = (int)((v - lo) * inv_w);
    return min(max(q, 0), maxq);
}

__global__ void key_hist_kernel(const float4* __restrict__ coords,
                                const float4* __restrict__ refc) {
    int i = blockIdx.x * blockDim.x + threadIdx.x;
    float ux, uy, uz, ut;
    compute_u(coords[i], refc[i], ux, uy, uz, ut);
    // bits: x=3, y=3, z=3, t=7 (t spans ~16x more cells than x per level)
    unsigned qx = quantn(ux, 0.7444f, 8.0f   / 0.0112f, 7);
    unsigned qy = quantn(uy, 0.7472f, 8.0f   / 0.0056f, 7);
    unsigned qz = quantn(uz, 0.7700f, 8.0f   / 0.0100f, 7);
    unsigned qt = quantn(ut, 0.0500f, 128.0f / 0.1800f, 127);
    // interleave LSB->MSB: t0 t1 x0 y0 z0 t2 t3 x1 y1 z1 t4 t5 x2 y2 z2 t6
    unsigned key =
          (qt & 3u)
        | ((qx & 1u) << 2) | ((qy & 1u) << 3) | ((qz & 1u) << 4)
        | (((qt >> 2) & 3u) << 5)
        | (((qx >> 1) & 1u) << 7) | (((qy >> 1) & 1u) << 8) | (((qz >> 1) & 1u) << 9)
        | (((qt >> 4) & 3u) << 10)
        | (((qx >> 2) & 1u) << 12) | (((qy >> 2) & 1u) << 13) | (((qz >> 2) & 1u) << 14)
        | (((qt >> 6) & 1u) << 15);
    g_key[i] = (unsigned short)key;
    atomicAdd(&g_hist[key], 1);
}

// A: per-block sums of 256-bin chunks (coalesced)
__global__ __launch_bounds__(256) void scanA_kernel() {
    __shared__ int s[256];
    int t = threadIdx.x;
    int v = g_hist[blockIdx.x * 256 + t];
    s[t] = v;
    __syncthreads();
    for (int off = 128; off > 0; off >>= 1) {
        if (t < off) s[t] += s[t + off];
        __syncthreads();
    }
    if (t == 0) g_bsum[blockIdx.x] = s[0];
}

// B: exclusive scan of 256 block sums (single block)
__global__ __launch_bounds__(256) void scanB_kernel() {
    __shared__ int s[256];
    int t = threadIdx.x;
    int v = g_bsum[t];
    s[t] = v;
    __syncthreads();
    for (int off = 1; off < 256; off <<= 1) {
        int x = (t >= off) ? s[t - off] : 0;
        __syncthreads();
        s[t] += x;
        __syncthreads();
    }
    g_bsum[t] = s[t] - v;   // exclusive
}

// C: per-chunk exclusive scan + chunk offset (coalesced)
__global__ __launch_bounds__(256) void scanC_kernel() {
    __shared__ int s[256];
    int t = threadIdx.x;
    int bin = blockIdx.x * 256 + t;
    int v = g_hist[bin];
    s[t] = v;
    __syncthreads();
    for (int off = 1; off < 256; off <<= 1) {
        int x = (t >= off) ? s[t - off] : 0;
        __syncthreads();
        s[t] += x;
        __syncthreads();
    }
    g_hist[bin] = s[t] - v + g_bsum[blockIdx.x];
}

__global__ void scatter_kernel() {
    int i = blockIdx.x * blockDim.x + threadIdx.x;
    int pos = atomicAdd(&g_hist[g_key[i]], 1);
    g_perm[pos] = i;
}

// ---------------- main encode kernels ----------------

template <int L0, int NLEV, bool USE_PERM>
__global__ __launch_bounds__(256) void energy4d_group_kernel(
    const float4* __restrict__ coords,
    const float4* __restrict__ refc,
    const float2* __restrict__ t0,
    const float2* __restrict__ t1,
    const float2* __restrict__ t2,
    const float2* __restrict__ t3,
    float2* __restrict__ out)   // out as float2: elem = pt*64 + e*16 + l
{
    const int warp = threadIdx.x >> 5;
    const int lane = threadIdx.x & 31;
    const int e    = warp & 3;                               // encoding id
    const int slot = (blockIdx.x * 2 + (warp >> 2)) * 32 + lane;
    const int pt   = USE_PERM ? g_perm[slot] : slot;

    uint64_t pol;
    asm("createpolicy.fractional.L2::evict_last.b64 %0, 1.0;" : "=l"(pol));

    float ux, uy, uz, ut;
    compute_u(coords[pt], refc[pt], ux, uy, uz, ut);

    // encoding dim selection: e0=(x,y,z) e1=(x,y,t) e2=(y,z,t) e3=(x,z,t)
    const float ua = (e == 2) ? uy : ux;
    const float ub = (e <= 1) ? uy : uz;
    const float uc = (e == 0) ? uz : ut;
    const float2* __restrict__ tbl =
        (e == 0) ? t0 : (e == 1) ? t1 : (e == 2) ? t2 : t3;

    float2 acc[NLEV];

    #pragma unroll
    for (int j = 0; j < NLEV; ++j) {
        const int   l     = L0 + j;
        const int   res   = 32 << l;
        const float resm1 = (float)(res - 1);
        const int   off   = level_offset(l);

        float pa = __fmul_rn(ua, resm1);
        float pb = __fmul_rn(ub, resm1);
        float pc = __fmul_rn(uc, resm1);
        int a0 = min(max((int)floorf(pa), 0), res - 2);
        int b0 = min(max((int)floorf(pb), 0), res - 2);
        int c0 = min(max((int)floorf(pc), 0), res - 2);
        float wa = __fsub_rn(pa, (float)a0);
        float wb = __fsub_rn(pb, (float)b0);
        float wc = __fsub_rn(pc, (float)c0);

        int idx[8];
        if (l >= 2) {
            unsigned ha0 = (unsigned)a0,      ha1 = ha0 + 1u;
            unsigned hb0 = (unsigned)b0 * P1, hb1 = hb0 + P1;
            unsigned hc0 = (unsigned)c0 * P2, hc1 = hc0 + P2;
            idx[0] = (int)((ha0 ^ hb0 ^ hc0) & HMASK) + off;
            idx[1] = (int)((ha1 ^ hb0 ^ hc0) & HMASK) + off;
            idx[2] = (int)((ha0 ^ hb1 ^ hc0) & HMASK) + off;
            idx[3] = (int)((ha1 ^ hb1 ^ hc0) & HMASK) + off;
            idx[4] = (int)((ha0 ^ hb0 ^ hc1) & HMASK) + off;
            idx[5] = (int)((ha1 ^ hb0 ^ hc1) & HMASK) + off;
            idx[6] = (int)((ha0 ^ hb1 ^ hc1) & HMASK) + off;
            idx[7] = (int)((ha1 ^ hb1 ^ hc1) & HMASK) + off;
        } else {
            const int rr = res * res;
            int base = a0 + res * (b0 + res * c0) + off;
            idx[0] = base;
            idx[1] = base + 1;
            idx[2] = base + res;
            idx[3] = base + res + 1;
            idx[4] = base + rr;
            idx[5] = base + rr + 1;
            idx[6] = base + rr + res;
            idx[7] = base + rr + res + 1;
        }

        float2 f[8];
        #pragma unroll
        for (int i = 0; i < 8; ++i) f[i] = ldg_tbl(&tbl[idx[i]], pol);

        const float oma = __fsub_rn(1.0f, wa);
        const float omb = __fsub_rn(1.0f, wb);
        const float omc = __fsub_rn(1.0f, wc);
        float accx = 0.0f, accy = 0.0f;
        #pragma unroll
        for (int i = 0; i < 8; ++i) {
            float cwa = (i & 1) ? wa : oma;
            float cwb = (i & 2) ? wb : omb;
            float cwc = (i & 4) ? wc : omc;
            float cw  = __fmul_rn(__fmul_rn(cwa, cwb), cwc);
            accx = __fadd_rn(accx, __fmul_rn(f[i].x, cw));
            accy = __fadd_rn(accy, __fmul_rn(f[i].y, cw));
        }
        acc[j] = make_float2(accx, accy);
    }

    float2* optr = out + (size_t)pt * 64 + (size_t)e * 16 + L0;
    #pragma unroll
    for (int j = 0; j < NLEV; j += 2) {
        st_cs4((float4*)(optr + j),
               make_float4(acc[j].x, acc[j].y, acc[j + 1].x, acc[j + 1].y));
    }
}

extern "C" void kernel_launch(void* const* d_in, const int* in_sizes, int n_in,
                              void* d_out, int out_size) {
    const int n = in_sizes[0] / 4;          // number of points (262144)
    const float4* coords = (const float4*)d_in[0];
    const float4* refc   = (const float4*)d_in[1];
    const float2* t0 = (const float2*)d_in[2];
    const float2* t1 = (const float2*)d_in[3];
    const float2* t2 = (const float2*)d_in[4];
    const float2* t3 = (const float2*)d_in[5];
    float2* out = (float2*)d_out;

    // counting sort by 16-bit Morton key (all parallel & coalesced)
    zero_hist_kernel<<<NBINS / 256, 256>>>();
    key_hist_kernel<<<n / 256, 256>>>(coords, refc);
    scanA_kernel<<<256, 256>>>();
    scanB_kernel<<<1, 256>>>();
    scanC_kernel<<<256, 256>>>();
    scatter_kernel<<<n / 256, 256>>>();

    dim3 block(256);                        // 8 warps = 2 pt-groups x 4 encodings
    dim3 grid(n / 64);
    energy4d_group_kernel<0,  4, true ><<<grid, block>>>(coords, refc, t0, t1, t2, t3, out);
    energy4d_group_kernel<4,  4, true ><<<grid, block>>>(coords, refc, t0, t1, t2, t3, out);
    energy4d_group_kernel<8,  4, true ><<<grid, block>>>(coords, refc, t0, t1, t2, t3, out);
    energy4d_group_kernel<12, 4, false><<<grid, block>>>(coords, refc, t0, t1, t2, t3, out);
}